// round 5
// baseline (speedup 1.0000x reference)
#include <cuda_runtime.h>
#include <cstdint>

// Problem constants (fixed by the reference)
#define BB 8
#define TT 512
#define DD 512
#define D4 (DD / 4)            // 128 float4 per frame
#define FRAME_BYTES (DD * 4)   // 2048 B
#define MAX_LEN 7680           // TT * 15

#define GCTA (MAX_LEN / 16)        // 480 gather CTAs per batch (16 frames each)
#define ZCTA_FRAMES 128            // frames owned per zero CTA
#define NZCTA (MAX_LEN / ZCTA_FRAMES)  // 60 zero CTAs per batch
#define ZBUF_BYTES 16384           // zeroed SMEM staging (16 KB)

// Scratch (static device globals; no allocation):
__device__ int g_idx[BB * MAX_LEN];  // frame -> phoneme (valid prefix only)
__device__ int g_total[BB];          // per-batch valid length

// ---------------------------------------------------------------------------
// Kernel 1: shfl-scan of max(dur,1) + scatter-fill of g_idx valid prefix.
// One block per batch, 512 threads, 2 barriers.
// ---------------------------------------------------------------------------
__global__ void __launch_bounds__(TT) scan_fill_kernel(const int* __restrict__ dur) {
    const int b = blockIdx.x, t = threadIdx.x;
    const int lane = t & 31, w = t >> 5;

    int v = dur[b * TT + t];
    v = (v < 1) ? 1 : v;

    int x = v;
#pragma unroll
    for (int o = 1; o < 32; o <<= 1) {
        int y = __shfl_up_sync(0xFFFFFFFFu, x, o);
        if (lane >= o) x += y;
    }
    __shared__ int wsum[16];
    if (lane == 31) wsum[w] = x;
    __syncthreads();
    if (w == 0) {
        int s = (lane < 16) ? wsum[lane] : 0;
#pragma unroll
        for (int o = 1; o < 16; o <<= 1) {
            int y = __shfl_up_sync(0xFFFFFFFFu, s, o);
            if (lane >= o) s += y;
        }
        if (lane < 16) wsum[lane] = s;
    }
    __syncthreads();
    const int end   = ((w > 0) ? wsum[w - 1] : 0) + x;  // inclusive cumsum
    const int start = end - v;

    int* __restrict__ row = g_idx + b * MAX_LEN;
    for (int i = start; i < end; i++) row[i] = t;   // <= 15 stores
    if (t == TT - 1) g_total[b] = end;
}

// ---------------------------------------------------------------------------
// Kernel 2: hybrid expand.
//  blockIdx.x <  GCTA : gather CTA — (128,4) threads, 16 frames, valid only.
//  blockIdx.x >= GCTA : zero CTA  — bulk-stores zeros over its tail slice.
// ---------------------------------------------------------------------------
__global__ void __launch_bounds__(512) expand_kernel(
    const float4* __restrict__ feat,  // (B, T, D/4)
    float4* __restrict__ out)         // (B, MAX_LEN, D/4)
{
    __shared__ alignas(128) float4 szero[ZBUF_BYTES / 16];  // 16 KB

    const int b = blockIdx.y;
    const int total = __ldg(&g_total[b]);

    if (blockIdx.x < GCTA) {
        // ---- gather role: frames base + 4*j, j<4 ----
        const int base = blockIdx.x * 16 + threadIdx.y;
        const int lane = threadIdx.x;  // 0..127

        const int* __restrict__ row = g_idx + b * MAX_LEN;
        const float4* __restrict__ fb = feat + (size_t)b * TT * D4;
        float4* __restrict__ ob = out + ((size_t)b * MAX_LEN + base) * D4 + lane;

        int idx[4];
#pragma unroll
        for (int j = 0; j < 4; j++) {
            const int n = base + 4 * j;
            idx[j] = (n < total) ? __ldg(&row[n]) : -1;
        }
        float4 val[4];
#pragma unroll
        for (int j = 0; j < 4; j++)
            if (idx[j] >= 0) val[j] = __ldg(fb + (size_t)idx[j] * D4 + lane);
#pragma unroll
        for (int j = 0; j < 4; j++)
            if (idx[j] >= 0) ob[(size_t)4 * j * D4] = val[j];
        return;
    }

    // ---- zero role: bulk-store zeros over slice ∩ [total, MAX_LEN) ----
    const int z = blockIdx.x - GCTA;          // 0..NZCTA-1
    const int tid = threadIdx.x + threadIdx.y * 128;

    const float4 z4 = make_float4(0.f, 0.f, 0.f, 0.f);
#pragma unroll
    for (int i = 0; i < (ZBUF_BYTES / 16) / 512; i++)
        szero[tid + 512 * i] = z4;
    __syncthreads();

    if (tid == 0) {
        int lo = z * ZCTA_FRAMES;
        const int hi = lo + ZCTA_FRAMES;
        if (lo < total) lo = total;
        if (hi > lo) {
            asm volatile("fence.proxy.async.shared::cta;" ::: "memory");
            const uint32_t s_z = (uint32_t)__cvta_generic_to_shared(szero);
            char* g = (char*)out + ((size_t)b * MAX_LEN + lo) * FRAME_BYTES;
            size_t nbytes = (size_t)(hi - lo) * FRAME_BYTES;
            while (nbytes > 0) {
                const uint32_t chunk =
                    nbytes > ZBUF_BYTES ? (uint32_t)ZBUF_BYTES : (uint32_t)nbytes;
                asm volatile(
                    "cp.async.bulk.global.shared::cta.bulk_group [%0], [%1], %2;"
                    :: "l"(g), "r"(s_z), "r"(chunk) : "memory");
                g += chunk;
                nbytes -= chunk;
            }
            asm volatile("cp.async.bulk.commit_group;" ::: "memory");
            asm volatile("cp.async.bulk.wait_group 0;" ::: "memory");
        }
    }
}

// ---------------------------------------------------------------------------
// Launch
// ---------------------------------------------------------------------------
extern "C" void kernel_launch(void* const* d_in, const int* in_sizes, int n_in,
                              void* d_out, int out_size) {
    const float4* feat = (const float4*)d_in[0];  // features (8,512,512) f32
    const int*    dur  = (const int*)d_in[1];     // durations (8,512) i32
    float4*       out  = (float4*)d_out;          // (8,7680,512) f32

    (void)in_sizes; (void)n_in; (void)out_size;

    scan_fill_kernel<<<BB, TT>>>(dur);

    dim3 block(128, 4, 1);
    dim3 grid(GCTA + NZCTA, BB, 1);
    expand_kernel<<<grid, block>>>(feat, out);
}

// round 8
// speedup vs baseline: 2.2692x; 2.2692x over previous
#include <cuda_runtime.h>
#include <cstdint>

// Problem constants (fixed by the reference)
#define BB 8
#define TT 512
#define DD 512
#define D4 (DD / 4)       // 128 float4 per frame
#define MAX_LEN 7680      // TT * 15

// ---------------------------------------------------------------------------
// Single fused kernel: per-CTA duration scan + searchsorted + gather-expand.
// Grid (480, 8), block 512 (1D). Each CTA handles 16 output frames of batch b.
//   Phase 1: shfl block-scan of max(dur,1) into SMEM cum (2 barriers).
//   Phase 2: 16 threads binary-search SMEM cum for the 16 frame indices.
//   Phase 3: (128 lanes x 4 groups) x 4 frames each — float4 gather/store,
//            zero-fill past the valid length. Streaming stores.
// ---------------------------------------------------------------------------
__global__ void __launch_bounds__(512) fused_expand_kernel(
    const float4* __restrict__ feat,  // (B, T, D/4)
    const int*    __restrict__ dur,   // (B, T)
    float4*       __restrict__ out)   // (B, MAX_LEN, D/4)
{
    __shared__ int cum[TT];
    __shared__ int wsum[16];
    __shared__ int sidx[16];

    const int b     = blockIdx.y;
    const int base0 = blockIdx.x * 16;
    const int tid   = threadIdx.x;          // 0..511
    const int lane5 = tid & 31, w = tid >> 5;

    // ---- Phase 1: inclusive scan of clamped durations ----
    int v = __ldg(&dur[b * TT + tid]);
    v = (v < 1) ? 1 : v;
    int x = v;
#pragma unroll
    for (int o = 1; o < 32; o <<= 1) {
        int y = __shfl_up_sync(0xFFFFFFFFu, x, o);
        if (lane5 >= o) x += y;
    }
    if (lane5 == 31) wsum[w] = x;
    __syncthreads();
    if (w == 0) {
        int s = (lane5 < 16) ? wsum[lane5] : 0;
#pragma unroll
        for (int o = 1; o < 16; o <<= 1) {
            int y = __shfl_up_sync(0xFFFFFFFFu, s, o);
            if (lane5 >= o) s += y;
        }
        if (lane5 < 16) wsum[lane5] = s;
    }
    __syncthreads();
    cum[tid] = ((w > 0) ? wsum[w - 1] : 0) + x;
    __syncthreads();

    const int total = cum[TT - 1];

    // ---- Phase 2: frame -> phoneme via binary search in SMEM ----
    if (tid < 16) {
        const int n = base0 + tid;
        int r = -1;
        if (n < total) {
            // first i with cum[i] > n  (searchsorted side="right").
            // NOTE: range 512 needs 10 bisection steps (size can still be 1
            // after 9); keep the while-loop form.
            int lo = 0, hi = TT;
            while (lo < hi) {
                const int mid = (lo + hi) >> 1;
                if (cum[mid] <= n) lo = mid + 1; else hi = mid;
            }
            r = lo;
        }
        sidx[tid] = r;
    }
    __syncthreads();

    // ---- Phase 3: gather-expand (R3 layout) ----
    const int y    = tid >> 7;   // 0..3
    const int lane = tid & 127;  // 0..127
    const int base = base0 + y;

    const float4* __restrict__ fb = feat + (size_t)b * TT * D4;
    float4* __restrict__ ob = out + ((size_t)b * MAX_LEN + base) * D4 + lane;

    int idx[4];
#pragma unroll
    for (int j = 0; j < 4; j++)
        idx[j] = sidx[y + 4 * j];            // SMEM broadcast

    float4 val[4];
    const float4 zero = make_float4(0.f, 0.f, 0.f, 0.f);
#pragma unroll
    for (int j = 0; j < 4; j++)
        val[j] = (idx[j] >= 0) ? __ldg(fb + (size_t)idx[j] * D4 + lane) : zero;

#pragma unroll
    for (int j = 0; j < 4; j++)
        __stcs(&ob[(size_t)4 * j * D4], val[j]);   // streaming store
}

// ---------------------------------------------------------------------------
// Launch
// ---------------------------------------------------------------------------
extern "C" void kernel_launch(void* const* d_in, const int* in_sizes, int n_in,
                              void* d_out, int out_size) {
    const float4* feat = (const float4*)d_in[0];  // features (8,512,512) f32
    const int*    dur  = (const int*)d_in[1];     // durations (8,512) i32
    float4*       out  = (float4*)d_out;          // (8,7680,512) f32

    (void)in_sizes; (void)n_in; (void)out_size;

    dim3 grid(MAX_LEN / 16, BB, 1);
    fused_expand_kernel<<<grid, 512>>>(feat, dur, out);
}

// round 9
// speedup vs baseline: 2.4270x; 1.0695x over previous
#include <cuda_runtime.h>
#include <cstdint>

// Problem constants (fixed by the reference)
#define BB 8
#define TT 512
#define DD 512
#define D4 (DD / 4)       // 128 float4 per frame
#define MAX_LEN 7680      // TT * 15
#define FR 32             // output frames per CTA

// ---------------------------------------------------------------------------
// Single fused kernel. Grid (240, 8), block 512.
//   Phase 1: shfl block-scan of max(dur,1); each thread keeps [start,end).
//   Phase 2: scatter — thread t writes t into sidx for frames it owns that
//            fall inside this CTA's window (replaces binary search; frames
//            past the valid length keep the -1 pre-init).
//   Phase 3: two 16-frame gather waves, (128 lanes x 4) x 4 frames each,
//            float4 loads + streaming stores, zero-fill where sidx < 0.
// ---------------------------------------------------------------------------
__global__ void __launch_bounds__(512) fused_expand_kernel(
    const float4* __restrict__ feat,  // (B, T, D/4)
    const int*    __restrict__ dur,   // (B, T)
    float4*       __restrict__ out)   // (B, MAX_LEN, D/4)
{
    __shared__ int wsum[16];
    __shared__ int sidx[FR];

    const int b     = blockIdx.y;
    const int base0 = blockIdx.x * FR;
    const int tid   = threadIdx.x;          // 0..511
    const int lane5 = tid & 31, w = tid >> 5;

    // Pre-init sidx (ordered before scatter by the scan barriers).
    if (tid < FR) sidx[tid] = -1;

    // ---- Phase 1: inclusive scan of clamped durations ----
    int v = __ldg(&dur[b * TT + tid]);
    v = (v < 1) ? 1 : v;
    int x = v;
#pragma unroll
    for (int o = 1; o < 32; o <<= 1) {
        int y = __shfl_up_sync(0xFFFFFFFFu, x, o);
        if (lane5 >= o) x += y;
    }
    if (lane5 == 31) wsum[w] = x;
    __syncthreads();
    if (w == 0) {
        int s = (lane5 < 16) ? wsum[lane5] : 0;
#pragma unroll
        for (int o = 1; o < 16; o <<= 1) {
            int y = __shfl_up_sync(0xFFFFFFFFu, s, o);
            if (lane5 >= o) s += y;
        }
        if (lane5 < 16) wsum[lane5] = s;
    }
    __syncthreads();
    const int end   = ((w > 0) ? wsum[w - 1] : 0) + x;  // inclusive cumsum
    const int start = end - v;

    // ---- Phase 2: scatter phoneme id into this CTA's frame window ----
    {
        int lo = (start > base0) ? start : base0;
        const int hi = (end < base0 + FR) ? end : (base0 + FR);
        for (int i = lo; i < hi; i++) sidx[i - base0] = tid;
    }
    __syncthreads();

    // ---- Phase 3: gather-expand, two 16-frame waves ----
    const int y    = tid >> 7;   // 0..3
    const int lane = tid & 127;  // 0..127
    const float4* __restrict__ fb = feat + (size_t)b * TT * D4;
    const float4 zero = make_float4(0.f, 0.f, 0.f, 0.f);

#pragma unroll
    for (int half = 0; half < 2; half++) {
        const int fbase = base0 + 16 * half + y;
        float4* __restrict__ ob =
            out + ((size_t)b * MAX_LEN + fbase) * D4 + lane;

        int idx[4];
#pragma unroll
        for (int j = 0; j < 4; j++)
            idx[j] = sidx[16 * half + y + 4 * j];     // SMEM broadcast

        float4 val[4];
#pragma unroll
        for (int j = 0; j < 4; j++)
            val[j] = (idx[j] >= 0) ? __ldg(fb + (size_t)idx[j] * D4 + lane)
                                   : zero;
#pragma unroll
        for (int j = 0; j < 4; j++)
            __stcs(&ob[(size_t)4 * j * D4], val[j]);  // streaming store
    }
}

// ---------------------------------------------------------------------------
// Launch
// ---------------------------------------------------------------------------
extern "C" void kernel_launch(void* const* d_in, const int* in_sizes, int n_in,
                              void* d_out, int out_size) {
    const float4* feat = (const float4*)d_in[0];  // features (8,512,512) f32
    const int*    dur  = (const int*)d_in[1];     // durations (8,512) i32
    float4*       out  = (float4*)d_out;          // (8,7680,512) f32

    (void)in_sizes; (void)n_in; (void)out_size;

    dim3 grid(MAX_LEN / FR, BB, 1);
    fused_expand_kernel<<<grid, 512>>>(feat, dur, out);
}